// round 2
// baseline (speedup 1.0000x reference)
#include <cuda_runtime.h>
#include <cuda_fp16.h>
#include <cstdint>

#define NTOT   100000
#define KNEI   16
#define XNIN   128
#define XEIN   64
#define XNOUT  128
#define KTOT   320      // 128 (x) + 128 (xnj) + 64 (xej)
#define AS     328      // smem row stride in halves (padded: bank = 4g+tg, conflict-free)
#define ROWS_PER_CTA 128

// Scratch (device globals — allocation-free per harness rules)
__device__ __half g_xh[(size_t)NTOT * XNIN];     // fp16 copy of x (25.6 MB)
__device__ __half g_wh[XNOUT * KTOT];            // packed fp16 [Wc|Wn|We], row-major (n, k)

// ---------------------------------------------------------------------------
// Kernel 1: quantize x -> fp16, pack weights -> fp16
// ---------------------------------------------------------------------------
__global__ void prep_kernel(const float* __restrict__ x,
                            const float* __restrict__ Wc,
                            const float* __restrict__ Wn,
                            const float* __restrict__ We) {
    int tid = blockIdx.x * blockDim.x + threadIdx.x;
    int stride = gridDim.x * blockDim.x;

    const float4* x4 = (const float4*)x;
    __half2* xh2 = (__half2*)g_xh;
    const int total4 = NTOT * XNIN / 4;
    for (int i = tid; i < total4; i += stride) {
        float4 v = x4[i];
        xh2[2 * i]     = __floats2half2_rn(v.x, v.y);
        xh2[2 * i + 1] = __floats2half2_rn(v.z, v.w);
    }

    for (int i = tid; i < XNOUT * KTOT; i += stride) {
        int n = i / KTOT, k = i % KTOT;
        float w = (k < 128) ? Wc[n * 128 + k]
                : (k < 256) ? Wn[n * 128 + (k - 128)]
                            : We[n * 64 + (k - 256)];
        g_wh[i] = __float2half(w);
    }
}

// ---------------------------------------------------------------------------
// Kernel 2: fused A-tile build (x | gather-mean | e-mean) + fp16 MMA + relu
// ---------------------------------------------------------------------------
extern __shared__ __half smem[];

__global__ void __launch_bounds__(256, 1)
fused_kernel(const float* __restrict__ e,
             const int* __restrict__ ij,      // int32! (JAX x64 disabled)
             float* __restrict__ out) {
    __half* Asm = smem;                       // [128][AS]
    __half* Wsm = smem + ROWS_PER_CTA * AS;   // [128][AS]

    const int tid  = threadIdx.x;
    const int lane = tid & 31;
    const int warp = tid >> 5;
    const int r0   = blockIdx.x * ROWS_PER_CTA;

    // ---- Phase W: copy packed weights into smem (row-major n, stride AS) ----
    {
        const int4* wsrc = (const int4*)g_wh;   // 40960 halves = 5120 int4
        for (int i = tid; i < 5120; i += 256) {
            int row = i / 40, c = i % 40;       // 40 int4 per 320-half row
            *(int4*)&Wsm[row * AS + c * 8] = wsrc[i];
        }
    }

    // ---- Phase X: A[:, 0:128] = x_h rows ----
    for (int i = tid; i < 2048; i += 256) {     // 128 rows * 16 int4
        int m = i >> 4, c = i & 15;
        int r = r0 + m;
        int4 v = make_int4(0, 0, 0, 0);
        if (r < NTOT) v = *(const int4*)&g_xh[(size_t)r * 128 + c * 8];
        *(int4*)&Asm[m * AS + c * 8] = v;
    }

    // ---- Phase E: A[:, 256:320] = mean_k e[r, k, :] ----
    {
        const int j = tid & 15;                 // col group: 4j..4j+3
        const int mbase = tid >> 4;             // 16 rows concurrently
        #pragma unroll 1
        for (int it = 0; it < 8; it++) {
            int m = mbase + it * 16;
            int r = r0 + m;
            float4 s = make_float4(0.f, 0.f, 0.f, 0.f);
            if (r < NTOT) {
                const float4* ep = (const float4*)(e + (size_t)r * (KNEI * XEIN)) + j;
                #pragma unroll
                for (int k = 0; k < KNEI; k++) {
                    float4 v = ep[k * (XEIN / 4)];
                    s.x += v.x; s.y += v.y; s.z += v.z; s.w += v.w;
                }
            }
            __half2* dst = (__half2*)&Asm[m * AS + 256 + j * 4];
            dst[0] = __floats2half2_rn(s.x * 0.0625f, s.y * 0.0625f);
            dst[1] = __floats2half2_rn(s.z * 0.0625f, s.w * 0.0625f);
        }
    }

    // ---- Phase G: A[:, 128:256] = mean_k x_h[ nh[r,k] ]  (fp16 gather) ----
    {
        #pragma unroll 1
        for (int it = 0; it < 16; it++) {       // one warp per row, 8 rows/iter
            int m = warp + it * 8;
            int r = r0 + m;
            int idx = 0;
            if (r < NTOT && lane < KNEI)
                idx = ij[((size_t)r * KNEI + lane) * 2];   // ij[r, k, 0], int32
            float f0 = 0.f, f1 = 0.f, f2 = 0.f, f3 = 0.f;
            if (r < NTOT) {
                uint2 vals[KNEI];               // batch all 16 gathers (MLP=16)
                #pragma unroll
                for (int k = 0; k < KNEI; k++) {
                    int nb = __shfl_sync(0xffffffffu, idx, k);
                    nb = (nb < 0) ? 0 : ((nb >= NTOT) ? (NTOT - 1) : nb);  // defensive
                    vals[k] = *(const uint2*)&g_xh[(size_t)nb * 128 + lane * 4];
                }
                #pragma unroll
                for (int k = 0; k < KNEI; k++) {
                    __half2 h0 = *(__half2*)&vals[k].x;
                    __half2 h1 = *(__half2*)&vals[k].y;
                    float2 a = __half22float2(h0);
                    float2 b = __half22float2(h1);
                    f0 += a.x; f1 += a.y; f2 += b.x; f3 += b.y;
                }
            }
            __half2* dst = (__half2*)&Asm[m * AS + 128 + lane * 4];
            dst[0] = __floats2half2_rn(f0 * 0.0625f, f1 * 0.0625f);
            dst[1] = __floats2half2_rn(f2 * 0.0625f, f3 * 0.0625f);
        }
    }

    __syncthreads();

    // ---- Phase MMA: each warp computes 16 rows x 128 cols, K=320 ----
    const int g  = lane >> 2;     // groupID
    const int tg = lane & 3;      // thread-in-group
    const int wm = warp * 16;

    float acc[16][4];
    #pragma unroll
    for (int t = 0; t < 16; t++) {
        acc[t][0] = acc[t][1] = acc[t][2] = acc[t][3] = 0.f;
    }

    for (int k0 = 0; k0 < KTOT; k0 += 16) {
        uint32_t a0 = *(const uint32_t*)&Asm[(wm + g)     * AS + k0 +     tg * 2];
        uint32_t a1 = *(const uint32_t*)&Asm[(wm + g + 8) * AS + k0 +     tg * 2];
        uint32_t a2 = *(const uint32_t*)&Asm[(wm + g)     * AS + k0 + 8 + tg * 2];
        uint32_t a3 = *(const uint32_t*)&Asm[(wm + g + 8) * AS + k0 + 8 + tg * 2];
        #pragma unroll
        for (int t = 0; t < 16; t++) {
            uint32_t b0 = *(const uint32_t*)&Wsm[(t * 8 + g) * AS + k0 +     tg * 2];
            uint32_t b1 = *(const uint32_t*)&Wsm[(t * 8 + g) * AS + k0 + 8 + tg * 2];
            asm volatile(
                "mma.sync.aligned.m16n8k16.row.col.f32.f16.f16.f32 "
                "{%0,%1,%2,%3},{%4,%5,%6,%7},{%8,%9},{%0,%1,%2,%3};\n"
                : "+f"(acc[t][0]), "+f"(acc[t][1]), "+f"(acc[t][2]), "+f"(acc[t][3])
                : "r"(a0), "r"(a1), "r"(a2), "r"(a3), "r"(b0), "r"(b1));
        }
    }

    // ---- Store with relu ----
    #pragma unroll
    for (int t = 0; t < 16; t++) {
        int col  = t * 8 + tg * 2;
        int row0 = r0 + wm + g;
        int row1 = row0 + 8;
        if (row0 < NTOT) {
            float2 v;
            v.x = fmaxf(acc[t][0], 0.f);
            v.y = fmaxf(acc[t][1], 0.f);
            *(float2*)&out[(size_t)row0 * XNOUT + col] = v;
        }
        if (row1 < NTOT) {
            float2 v;
            v.x = fmaxf(acc[t][2], 0.f);
            v.y = fmaxf(acc[t][3], 0.f);
            *(float2*)&out[(size_t)row1 * XNOUT + col] = v;
        }
    }
}

// ---------------------------------------------------------------------------
extern "C" void kernel_launch(void* const* d_in, const int* in_sizes, int n_in,
                              void* d_out, int out_size) {
    const float* x  = (const float*)d_in[0];
    const float* e  = (const float*)d_in[1];
    const int*   ij = (const int*)d_in[2];     // int32 (JAX x64 disabled)
    const float* Wc = (const float*)d_in[3];
    const float* Wn = (const float*)d_in[4];
    const float* We = (const float*)d_in[5];
    float* out = (float*)d_out;
    (void)in_sizes; (void)n_in; (void)out_size;

    prep_kernel<<<2048, 256>>>(x, Wc, Wn, We);

    const int smem_bytes = 2 * ROWS_PER_CTA * AS * (int)sizeof(__half);  // 167936
    cudaFuncSetAttribute(fused_kernel,
                         cudaFuncAttributeMaxDynamicSharedMemorySize, smem_bytes);
    int nblk = (NTOT + ROWS_PER_CTA - 1) / ROWS_PER_CTA;   // 782
    fused_kernel<<<nblk, 256, smem_bytes>>>(e, ij, out);
}

// round 3
// speedup vs baseline: 1.5918x; 1.5918x over previous
#include <cuda_runtime.h>
#include <cuda_fp16.h>
#include <cstdint>

#define NTOT   100000
#define KNEI   16
#define XNIN   128
#define XEIN   64
#define XNOUT  128
#define KTOT   320      // 128 (x) + 128 (xnj) + 64 (xej)
#define AS     328      // smem row stride in halves: 164 words, 164%32=4 -> conflict-free
#define ROWS_PER_CTA 128

// Scratch (device globals — allocation-free per harness rules)
__device__ __half g_xh[(size_t)NTOT * XNIN];      // fp16 copy of x (25.6 MB)
__device__ __half g_A2[(size_t)NTOT * 192];       // fp16 [gather-mean(128) | e-mean(64)]
__device__ __half g_wh[XNOUT * KTOT];             // packed fp16 [Wc|Wn|We], row-major (n,k)

// ---------------------------------------------------------------------------
// Kernel 1: quantize x -> fp16, pack weights -> fp16
// ---------------------------------------------------------------------------
__global__ void prep_kernel(const float* __restrict__ x,
                            const float* __restrict__ Wc,
                            const float* __restrict__ Wn,
                            const float* __restrict__ We) {
    int tid = blockIdx.x * blockDim.x + threadIdx.x;
    int stride = gridDim.x * blockDim.x;

    const float4* x4 = (const float4*)x;
    __half2* xh2 = (__half2*)g_xh;
    const int total4 = NTOT * XNIN / 4;
    for (int i = tid; i < total4; i += stride) {
        float4 v = x4[i];
        xh2[2 * i]     = __floats2half2_rn(v.x, v.y);
        xh2[2 * i + 1] = __floats2half2_rn(v.z, v.w);
    }

    for (int i = tid; i < XNOUT * KTOT; i += stride) {
        int n = i / KTOT, k = i % KTOT;
        float w = (k < 128) ? Wc[n * 128 + k]
                : (k < 256) ? Wn[n * 128 + (k - 128)]
                            : We[n * 64 + (k - 256)];
        g_wh[i] = __float2half(w);
    }
}

// ---------------------------------------------------------------------------
// Kernel 2: build A2 = [ mean_k x_h[nh[r,k]] (128) | mean_k e[r,k,:] (64) ]
// One warp per row, grid-stride. Zero smem -> max occupancy, huge MLP.
// ---------------------------------------------------------------------------
__global__ void __launch_bounds__(256)
build_kernel(const float* __restrict__ e,
             const int* __restrict__ ij) {
    const int lane   = threadIdx.x & 31;
    const int warpId = (blockIdx.x * blockDim.x + threadIdx.x) >> 5;
    const int nWarps = (gridDim.x * blockDim.x) >> 5;

    for (int r = warpId; r < NTOT; r += nWarps) {
        // indices: ij[r, k, 0] for k = lane (< 16)
        int idx = 0;
        if (lane < KNEI) idx = __ldg(&ij[((size_t)r * KNEI + lane) * 2]);

        // ---- gather-mean: lane owns cols 4*lane .. 4*lane+3 ----
        uint2 vals[KNEI];
        #pragma unroll
        for (int k = 0; k < KNEI; k++) {
            int nb = __shfl_sync(0xffffffffu, idx, k);
            nb = (nb < 0) ? 0 : ((nb >= NTOT) ? (NTOT - 1) : nb);
            vals[k] = *(const uint2*)&g_xh[(size_t)nb * XNIN + lane * 4];
        }

        // ---- e-mean: lane owns cols 2*lane .. 2*lane+1 ----
        float2 evals[KNEI];
        const float* ebase = e + (size_t)r * (KNEI * XEIN) + lane * 2;
        #pragma unroll
        for (int k = 0; k < KNEI; k++)
            evals[k] = *(const float2*)(ebase + k * XEIN);

        float f0 = 0.f, f1 = 0.f, f2 = 0.f, f3 = 0.f;
        #pragma unroll
        for (int k = 0; k < KNEI; k++) {
            float2 a = __half22float2(*(__half2*)&vals[k].x);
            float2 b = __half22float2(*(__half2*)&vals[k].y);
            f0 += a.x; f1 += a.y; f2 += b.x; f3 += b.y;
        }
        float s0 = 0.f, s1 = 0.f;
        #pragma unroll
        for (int k = 0; k < KNEI; k++) { s0 += evals[k].x; s1 += evals[k].y; }

        __half* arow = &g_A2[(size_t)r * 192];
        uint2 gpack;
        *(__half2*)&gpack.x = __floats2half2_rn(f0 * 0.0625f, f1 * 0.0625f);
        *(__half2*)&gpack.y = __floats2half2_rn(f2 * 0.0625f, f3 * 0.0625f);
        *(uint2*)&arow[lane * 4] = gpack;
        *(__half2*)&arow[128 + lane * 2] = __floats2half2_rn(s0 * 0.0625f, s1 * 0.0625f);
    }
}

// ---------------------------------------------------------------------------
// Kernel 3: GEMM  out = relu( [xh | A2] @ [Wc|Wn|We]^T )
// 512 threads: 16 warps = 8 m-tiles x 2 n-halves. Coalesced loads only.
// ---------------------------------------------------------------------------
extern __shared__ __half smem[];

__global__ void __launch_bounds__(512, 1)
gemm_kernel(float* __restrict__ out) {
    __half* Asm = smem;                       // [128][AS]
    __half* Wsm = smem + ROWS_PER_CTA * AS;   // [128][AS]

    const int tid  = threadIdx.x;
    const int lane = tid & 31;
    const int warp = tid >> 5;
    const int r0   = blockIdx.x * ROWS_PER_CTA;

    // ---- W: packed weights -> smem (row-major n, stride AS) ----
    {
        const int4* wsrc = (const int4*)g_wh;   // 5120 int4
        for (int i = tid; i < 5120; i += 512) {
            int row = i / 40, c = i % 40;
            *(int4*)&Wsm[row * AS + c * 8] = wsrc[i];
        }
    }

    // ---- A[:, 0:128] = xh rows ----
    for (int i = tid; i < 2048; i += 512) {     // 128 rows * 16 int4
        int m = i >> 4, c = i & 15;
        int r = r0 + m;
        int4 v = make_int4(0, 0, 0, 0);
        if (r < NTOT) v = *(const int4*)&g_xh[(size_t)r * XNIN + c * 8];
        *(int4*)&Asm[m * AS + c * 8] = v;
    }

    // ---- A[:, 128:320] = A2 rows ----
    for (int i = tid; i < 3072; i += 512) {     // 128 rows * 24 int4
        int m = i / 24, c = i % 24;
        int r = r0 + m;
        int4 v = make_int4(0, 0, 0, 0);
        if (r < NTOT) v = *(const int4*)&g_A2[(size_t)r * 192 + c * 8];
        *(int4*)&Asm[m * AS + 128 + c * 8] = v;
    }

    __syncthreads();

    // ---- MMA: warp (mt, nh) computes rows [mt*16, +16) x cols [nh*64, +64) ----
    const int g  = lane >> 2;
    const int tg = lane & 3;
    const int mt = warp >> 1;
    const int nh = warp & 1;
    const int wm = mt * 16;

    float acc[8][4];
    #pragma unroll
    for (int t = 0; t < 8; t++)
        acc[t][0] = acc[t][1] = acc[t][2] = acc[t][3] = 0.f;

    #pragma unroll 4
    for (int k0 = 0; k0 < KTOT; k0 += 16) {
        uint32_t a0 = *(const uint32_t*)&Asm[(wm + g)     * AS + k0 +     tg * 2];
        uint32_t a1 = *(const uint32_t*)&Asm[(wm + g + 8) * AS + k0 +     tg * 2];
        uint32_t a2 = *(const uint32_t*)&Asm[(wm + g)     * AS + k0 + 8 + tg * 2];
        uint32_t a3 = *(const uint32_t*)&Asm[(wm + g + 8) * AS + k0 + 8 + tg * 2];
        #pragma unroll
        for (int t = 0; t < 8; t++) {
            int nrow = nh * 64 + t * 8 + g;
            uint32_t b0 = *(const uint32_t*)&Wsm[nrow * AS + k0 +     tg * 2];
            uint32_t b1 = *(const uint32_t*)&Wsm[nrow * AS + k0 + 8 + tg * 2];
            asm volatile(
                "mma.sync.aligned.m16n8k16.row.col.f32.f16.f16.f32 "
                "{%0,%1,%2,%3},{%4,%5,%6,%7},{%8,%9},{%0,%1,%2,%3};\n"
                : "+f"(acc[t][0]), "+f"(acc[t][1]), "+f"(acc[t][2]), "+f"(acc[t][3])
                : "r"(a0), "r"(a1), "r"(a2), "r"(a3), "r"(b0), "r"(b1));
        }
    }

    // ---- Store with relu ----
    #pragma unroll
    for (int t = 0; t < 8; t++) {
        int col  = nh * 64 + t * 8 + tg * 2;
        int row0 = r0 + wm + g;
        int row1 = row0 + 8;
        if (row0 < NTOT) {
            float2 v;
            v.x = fmaxf(acc[t][0], 0.f);
            v.y = fmaxf(acc[t][1], 0.f);
            *(float2*)&out[(size_t)row0 * XNOUT + col] = v;
        }
        if (row1 < NTOT) {
            float2 v;
            v.x = fmaxf(acc[t][2], 0.f);
            v.y = fmaxf(acc[t][3], 0.f);
            *(float2*)&out[(size_t)row1 * XNOUT + col] = v;
        }
    }
}

// ---------------------------------------------------------------------------
extern "C" void kernel_launch(void* const* d_in, const int* in_sizes, int n_in,
                              void* d_out, int out_size) {
    const float* x  = (const float*)d_in[0];
    const float* e  = (const float*)d_in[1];
    const int*   ij = (const int*)d_in[2];     // int32 (JAX x64 disabled)
    const float* Wc = (const float*)d_in[3];
    const float* Wn = (const float*)d_in[4];
    const float* We = (const float*)d_in[5];
    float* out = (float*)d_out;
    (void)in_sizes; (void)n_in; (void)out_size;

    prep_kernel<<<2048, 256>>>(x, Wc, Wn, We);

    build_kernel<<<2048, 256>>>(e, ij);

    const int smem_bytes = 2 * ROWS_PER_CTA * AS * (int)sizeof(__half);  // 167936
    cudaFuncSetAttribute(gemm_kernel,
                         cudaFuncAttributeMaxDynamicSharedMemorySize, smem_bytes);
    int nblk = (NTOT + ROWS_PER_CTA - 1) / ROWS_PER_CTA;   // 782
    gemm_kernel<<<nblk, 512, smem_bytes>>>(out);
}